// round 16
// baseline (speedup 1.0000x reference)
#include <cuda_runtime.h>
#include <cuda_fp16.h>
#include <math.h>

#define NN 50000
#define FF 48
#define CC 16     // H*C1 with H=1 -> softmax == 1, attention vanishes
#define L1 8

// ---------------- device scratch ----------------
__device__ __align__(32) __half g_yh[NN * CC];    // x @ W (fp16)
__device__ __align__(32) __half g_aggh[NN * CC];  // fp16 segment sum (self loop preloaded)
__device__ int g_degi[NN];   // in-degree; zeroed at load, self-cleaned by k_head
__device__ int g_is64;       // edge dtype flag, written by k_proj each run

// int64 node ids < 50000 => odd 32-bit words all zero over first 8 entries.
__device__ __forceinline__ bool detect64(const unsigned* __restrict__ ew) {
    unsigned v = 0u;
#pragma unroll
    for (int k = 0; k < 8; k++) v |= __ldg(&ew[2 * k + 1]);
    return v == 0u;
}

__device__ __forceinline__ void red_h8(__half* addr, uint4 v) {
    asm volatile("red.global.add.noftz.v4.f16x2 [%0], {%1,%2,%3,%4};"
                 :: "l"(addr), "r"(v.x), "r"(v.y), "r"(v.z), "r"(v.w) : "memory");
}

// ---------------- projection: y = x @ W, vector/register blocked ----------------
// 256 threads, 64 nodes/block, 4 threads/node, 4 outputs/thread.
// sX padded to 13 float4 per row to avoid 192B-stride bank conflicts.
__global__ void __launch_bounds__(256) k_proj(const float* __restrict__ x,
                                              const float* __restrict__ W,
                                              const void* __restrict__ ei,
                                              float* losss, int n) {
    __shared__ float4 sW4[FF * 4];      // 3 KB : W[k][4j..4j+3] at sW4[k*4+j]
    __shared__ float4 sX4[64 * 13];     // 13.3 KB (padded rows)
    if (blockIdx.x == 0 && threadIdx.x == 0) {
        if (losss) *losss = 0.0f;
        g_is64 = detect64((const unsigned*)ei) ? 1 : 0;
    }

    const int tid = threadIdx.x;
    for (int i = tid; i < FF * 4; i += 256) sW4[i] = ((const float4*)W)[i];

    int nodeBase = blockIdx.x * 64;
    const float4* Xv = (const float4*)x;
    int vbase = nodeBase * 12;          // 12 float4 per node row
    int vmax  = n * 12;
#pragma unroll
    for (int it = 0; it < 3; it++) {
        int i = it * 256 + tid;         // 0..767
        int row = i / 12, col = i - row * 12;
        float4 v = make_float4(0.f, 0.f, 0.f, 0.f);
        int g = vbase + i;
        if (g < vmax) v = Xv[g];
        sX4[row * 13 + col] = v;
    }
    __syncthreads();

    int ln   = tid >> 2;                // local node 0..63
    int jq   = tid & 3;                 // which c-quad (c = 4*jq .. 4*jq+3)
    int node = nodeBase + ln;
    if (node >= n) return;

    float a0 = 0.f, a1 = 0.f, a2 = 0.f, a3 = 0.f;
    const float4* xr = &sX4[ln * 13];
#pragma unroll
    for (int c4 = 0; c4 < 12; c4++) {
        float4 xv = xr[c4];
        int k = c4 * 4;
        float4 w0 = sW4[(k + 0) * 4 + jq];
        float4 w1 = sW4[(k + 1) * 4 + jq];
        float4 w2 = sW4[(k + 2) * 4 + jq];
        float4 w3 = sW4[(k + 3) * 4 + jq];
        a0 = fmaf(xv.x, w0.x, a0); a1 = fmaf(xv.x, w0.y, a1);
        a2 = fmaf(xv.x, w0.z, a2); a3 = fmaf(xv.x, w0.w, a3);
        a0 = fmaf(xv.y, w1.x, a0); a1 = fmaf(xv.y, w1.y, a1);
        a2 = fmaf(xv.y, w1.z, a2); a3 = fmaf(xv.y, w1.w, a3);
        a0 = fmaf(xv.z, w2.x, a0); a1 = fmaf(xv.z, w2.y, a1);
        a2 = fmaf(xv.z, w2.z, a2); a3 = fmaf(xv.z, w2.w, a3);
        a0 = fmaf(xv.w, w3.x, a0); a1 = fmaf(xv.w, w3.y, a1);
        a2 = fmaf(xv.w, w3.z, a2); a3 = fmaf(xv.w, w3.w, a3);
    }
    __half2 h01 = __floats2half2_rn(a0, a1);
    __half2 h23 = __floats2half2_rn(a2, a3);
    uint2 pack;
    pack.x = *(unsigned*)&h01;
    pack.y = *(unsigned*)&h23;
    *(uint2*)&g_yh[node * CC + jq * 4]   = pack;
    *(uint2*)&g_aggh[node * CC + jq * 4] = pack;   // self-loop contribution
}

// ---------------- edge scatter: consecutive-edge pairs, vector idx loads ----------------
// thread t: pair = t>>1 (edges 2p, 2p+1), q = t&1 (which 16B half-row).
// Both q-lanes of a pair load the same idx vector (broadcast). deg REDs on q0.
__global__ void __launch_bounds__(256) k_edge(const void* __restrict__ ei, int E) {
    int t = blockIdx.x * blockDim.x + threadIdx.x;
    int p = t >> 1;
    int e0 = 2 * p, e1 = 2 * p + 1;
    if (e0 >= E) return;
    bool h1 = e1 < E;
    int q0lane = !(t & 1);
    int qo = (t & 1) * 8;

    int s0, s1 = 0, d0, d1 = 0;
    if (g_is64) {
        const uint4* sp = (const uint4*)ei;                 // 2 int64 per uint4
        const long long* base = (const long long*)ei;
        uint4 sv = __ldg(&sp[p]);
        s0 = (int)sv.x; s1 = (int)sv.z;
        const uint4* dp = (const uint4*)(base + E);
        if ((E & 1) == 0) {
            uint4 dv = __ldg(&dp[p]);
            d0 = (int)dv.x; d1 = (int)dv.z;
        } else {                                            // unaligned fallback
            d0 = (int)__ldg(&base[E + e0]);
            if (h1) d1 = (int)__ldg(&base[E + e1]);
        }
    } else {
        const int2* sp = (const int2*)ei;
        const int* base = (const int*)ei;
        int2 sv = __ldg(&sp[p]);
        s0 = sv.x; s1 = sv.y;
        if ((E & 1) == 0) {
            int2 dv = __ldg((const int2*)(base + E) + p);
            d0 = dv.x; d1 = dv.y;
        } else {
            d0 = __ldg(&base[E + e0]);
            if (h1) d1 = __ldg(&base[E + e1]);
        }
    }
    // front-batched independent y loads
    uint4 y0 = __ldg((const uint4*)&g_yh[s0 * CC + qo]);
    uint4 y1 = __ldg((const uint4*)&g_yh[s1 * CC + qo]);
    red_h8(&g_aggh[d0 * CC + qo], y0);
    if (q0lane) atomicAdd(&g_degi[d0], 1);
    if (h1) {
        red_h8(&g_aggh[d1 * CC + qo], y1);
        if (q0lane) atomicAdd(&g_degi[d1], 1);
    }
}

// ---------------- head: 2 lanes per node; self-cleans g_degi ----------------
__global__ void k_head(const float* __restrict__ bias,
                       const float* __restrict__ l1w,  // [16,8]
                       const float* __restrict__ l1b,
                       const float* __restrict__ ow,   // [8,1]
                       const float* __restrict__ ob,
                       const float* __restrict__ labels,
                       const float* __restrict__ wts,
                       float* __restrict__ pout, float* losss,
                       int n, float inv_n) {
    __shared__ float sb[CC], sl1w[CC * L1], sl1b[L1], sow[L1], sob;
    if (threadIdx.x < CC) sb[threadIdx.x] = bias[threadIdx.x];
    if (threadIdx.x < CC * L1) sl1w[threadIdx.x] = l1w[threadIdx.x];
    if (threadIdx.x < L1) { sl1b[threadIdx.x] = l1b[threadIdx.x]; sow[threadIdx.x] = ow[threadIdx.x]; }
    if (threadIdx.x == 0) sob = ob[0];
    __syncthreads();

    int t = blockIdx.x * blockDim.x + threadIdx.x;
    int i = t >> 1;            // node
    int a = t & 1;             // which 8-channel half
    float term = 0.0f;
    if (i < n) {
        int degc = __ldg(&g_degi[i]);
        uint4 r = *(const uint4*)&g_aggh[i * CC + a * 8];
        if (a == 0) g_degi[i] = 0;                  // reset for next graph replay
        float invdeg = __fdividef(1.0f, (float)(degc + 1));   // + self loop
        float h[8];
        {
            const unsigned rr[4] = {r.x, r.y, r.z, r.w};
#pragma unroll
            for (int k = 0; k < 4; k++) {
                float2 f = __half22float2(*(const __half2*)&rr[k]);
                h[2 * k]     = f.x;
                h[2 * k + 1] = f.y;
            }
        }
        int cbase = a * 8;
#pragma unroll
        for (int k = 0; k < 8; k++)
            h[k] = fmaxf(fmaf(h[k], invdeg, sb[cbase + k]), 0.0f);

        float s[L1];
#pragma unroll
        for (int j = 0; j < L1; j++) {
            float acc = 0.0f;
#pragma unroll
            for (int k = 0; k < 8; k++)
                acc = fmaf(h[k], sl1w[(cbase + k) * L1 + j], acc);
            s[j] = acc;
        }
        float z = 0.0f;
#pragma unroll
        for (int j = 0; j < L1; j++) {
            float sj = s[j] + __shfl_xor_sync(0xFFFFFFFFu, s[j], 1);
            float h2 = fmaxf(sj + sl1b[j], 0.0f);
            z = fmaf(h2, sow[j], z);
        }
        if (a == 0) {
            z += sob;
            float p = 1.0f / (1.0f + __expf(-z));
            pout[i] = p;
            const float eps = 1e-7f;
            float pc = fminf(fmaxf(p, eps), 1.0f - eps);
            float sel = (labels[i] > 0.5f) ? pc : (1.0f - pc);  // labels exactly 0/1
            term = wts[i] * (-__logf(sel)) * inv_n;
        }
    }
    // block reduce -> one atomic per block
#pragma unroll
    for (int off = 16; off > 0; off >>= 1)
        term += __shfl_down_sync(0xFFFFFFFFu, term, off);
    __shared__ float wsum[8];
    int wid = threadIdx.x >> 5, lid = threadIdx.x & 31;
    if (lid == 0) wsum[wid] = term;
    __syncthreads();
    if (threadIdx.x == 0 && losss) {
        float sum = 0.0f;
#pragma unroll
        for (int k = 0; k < (int)(blockDim.x >> 5); k++) sum += wsum[k];
        atomicAdd(losss, sum);
    }
}

// ---------------- launch ----------------
extern "C" void kernel_launch(void* const* d_in, const int* in_sizes, int n_in,
                              void* d_out, int out_size) {
    const float* x      = (const float*)d_in[0];
    const void*  ei     = d_in[1];
    const float* labels = (const float*)d_in[2];
    const float* wts    = (const float*)d_in[3];
    const float* W      = (const float*)d_in[4];
    // d_in[5]=u, d_in[6]=c unused (H=1 softmax == 1)
    const float* bias   = (const float*)d_in[7];
    const float* l1w    = (const float*)d_in[8];
    const float* l1b    = (const float*)d_in[9];
    const float* ow     = (const float*)d_in[10];
    const float* ob     = (const float*)d_in[11];

    int n = in_sizes[0] / FF;
    int E = in_sizes[1] / 2;

    float* out = (float*)d_out;
    int loss_slot = (out_size == n + 1) ? 1 : 0;
    float* pout  = loss_slot ? (out + 1) : out;
    float* losss = loss_slot ? out : (float*)0;

    k_proj<<<(n + 63) / 64, 256>>>(x, W, ei, losss, n);

    long long threads = ((long long)E + 1) / 2 * 2;   // 2 threads per edge pair
    k_edge<<<(int)((threads + 255) / 256), 256>>>(ei, E);

    k_head<<<(n * 2 + 255) / 256, 256>>>(bias, l1w, l1b, ow, ob, labels, wts,
                                         pout, losss, n, 1.0f / (float)n);
}

// round 17
// speedup vs baseline: 1.0525x; 1.0525x over previous
#include <cuda_runtime.h>
#include <cuda_fp16.h>
#include <math.h>

#define NN 50000
#define FF 48
#define CC 16     // H*C1 with H=1 -> softmax == 1, attention vanishes
#define L1 8

// ---------------- device scratch ----------------
__device__ __align__(32) __half g_yh[NN * CC];    // x @ W (fp16)
__device__ __align__(32) __half g_aggh[NN * CC];  // fp16 segment sum (self loop preloaded)
__device__ int g_degi[NN];   // in-degree; zeroed at load, self-cleaned by k_head
__device__ int g_is64;       // edge dtype flag, written by k_proj each run

// int64 node ids < 50000 => odd 32-bit words all zero over first 8 entries.
__device__ __forceinline__ bool detect64(const unsigned* __restrict__ ew) {
    unsigned v = 0u;
#pragma unroll
    for (int k = 0; k < 8; k++) v |= __ldg(&ew[2 * k + 1]);
    return v == 0u;
}

__device__ __forceinline__ void red_h8(__half* addr, uint4 v) {
    asm volatile("red.global.add.noftz.v4.f16x2 [%0], {%1,%2,%3,%4};"
                 :: "l"(addr), "r"(v.x), "r"(v.y), "r"(v.z), "r"(v.w) : "memory");
}

// ---------------- projection: y = x @ W, vector/register blocked ----------------
// 256 threads, 64 nodes/block, 4 threads/node, 4 outputs/thread.
// sX padded to 13 float4 per row to avoid 192B-stride bank conflicts.
__global__ void __launch_bounds__(256) k_proj(const float* __restrict__ x,
                                              const float* __restrict__ W,
                                              const void* __restrict__ ei,
                                              float* losss, int n) {
    __shared__ float4 sW4[FF * 4];      // 3 KB : W[k][4j..4j+3] at sW4[k*4+j]
    __shared__ float4 sX4[64 * 13];     // 13.3 KB (padded rows)
    if (blockIdx.x == 0 && threadIdx.x == 0) {
        if (losss) *losss = 0.0f;
        g_is64 = detect64((const unsigned*)ei) ? 1 : 0;
    }

    const int tid = threadIdx.x;
    for (int i = tid; i < FF * 4; i += 256) sW4[i] = ((const float4*)W)[i];

    int nodeBase = blockIdx.x * 64;
    const float4* Xv = (const float4*)x;
    int vbase = nodeBase * 12;          // 12 float4 per node row
    int vmax  = n * 12;
#pragma unroll
    for (int it = 0; it < 3; it++) {
        int i = it * 256 + tid;         // 0..767
        int row = i / 12, col = i - row * 12;
        float4 v = make_float4(0.f, 0.f, 0.f, 0.f);
        int g = vbase + i;
        if (g < vmax) v = Xv[g];
        sX4[row * 13 + col] = v;
    }
    __syncthreads();

    int ln   = tid >> 2;                // local node 0..63
    int jq   = tid & 3;                 // which c-quad (c = 4*jq .. 4*jq+3)
    int node = nodeBase + ln;
    if (node >= n) return;

    float a0 = 0.f, a1 = 0.f, a2 = 0.f, a3 = 0.f;
    const float4* xr = &sX4[ln * 13];
#pragma unroll
    for (int c4 = 0; c4 < 12; c4++) {
        float4 xv = xr[c4];
        int k = c4 * 4;
        float4 w0 = sW4[(k + 0) * 4 + jq];
        float4 w1 = sW4[(k + 1) * 4 + jq];
        float4 w2 = sW4[(k + 2) * 4 + jq];
        float4 w3 = sW4[(k + 3) * 4 + jq];
        a0 = fmaf(xv.x, w0.x, a0); a1 = fmaf(xv.x, w0.y, a1);
        a2 = fmaf(xv.x, w0.z, a2); a3 = fmaf(xv.x, w0.w, a3);
        a0 = fmaf(xv.y, w1.x, a0); a1 = fmaf(xv.y, w1.y, a1);
        a2 = fmaf(xv.y, w1.z, a2); a3 = fmaf(xv.y, w1.w, a3);
        a0 = fmaf(xv.z, w2.x, a0); a1 = fmaf(xv.z, w2.y, a1);
        a2 = fmaf(xv.z, w2.z, a2); a3 = fmaf(xv.z, w2.w, a3);
        a0 = fmaf(xv.w, w3.x, a0); a1 = fmaf(xv.w, w3.y, a1);
        a2 = fmaf(xv.w, w3.z, a2); a3 = fmaf(xv.w, w3.w, a3);
    }
    __half2 h01 = __floats2half2_rn(a0, a1);
    __half2 h23 = __floats2half2_rn(a2, a3);
    uint2 pack;
    pack.x = *(unsigned*)&h01;
    pack.y = *(unsigned*)&h23;
    *(uint2*)&g_yh[node * CC + jq * 4]   = pack;
    *(uint2*)&g_aggh[node * CC + jq * 4] = pack;   // self-loop contribution
}

// ---------------- edge scatter: consecutive-edge pairs, vector idx loads ----------------
// thread t: pair = t>>1 (edges 2p, 2p+1), q = t&1 (which 16B half-row).
// q0/q1 lanes of a pair share each y/agg 32B sector -> sector-optimal mapping.
// deg REDs issued by the q0 lane.
__global__ void __launch_bounds__(512) k_edge(const void* __restrict__ ei, int E) {
    int t = blockIdx.x * blockDim.x + threadIdx.x;
    int p = t >> 1;
    int e0 = 2 * p, e1 = 2 * p + 1;
    if (e0 >= E) return;
    bool h1 = e1 < E;
    int q0lane = !(t & 1);
    int qo = (t & 1) * 8;

    int s0, s1 = 0, d0, d1 = 0;
    if (g_is64) {
        const uint4* sp = (const uint4*)ei;                 // 2 int64 per uint4
        const long long* base = (const long long*)ei;
        uint4 sv = __ldg(&sp[p]);
        s0 = (int)sv.x; s1 = (int)sv.z;
        const uint4* dp = (const uint4*)(base + E);
        if ((E & 1) == 0) {
            uint4 dv = __ldg(&dp[p]);
            d0 = (int)dv.x; d1 = (int)dv.z;
        } else {                                            // unaligned fallback
            d0 = (int)__ldg(&base[E + e0]);
            if (h1) d1 = (int)__ldg(&base[E + e1]);
        }
    } else {
        const int2* sp = (const int2*)ei;
        const int* base = (const int*)ei;
        int2 sv = __ldg(&sp[p]);
        s0 = sv.x; s1 = sv.y;
        if ((E & 1) == 0) {
            int2 dv = __ldg((const int2*)(base + E) + p);
            d0 = dv.x; d1 = dv.y;
        } else {
            d0 = __ldg(&base[E + e0]);
            if (h1) d1 = __ldg(&base[E + e1]);
        }
    }
    // front-batched independent y loads
    uint4 y0 = __ldg((const uint4*)&g_yh[s0 * CC + qo]);
    uint4 y1 = __ldg((const uint4*)&g_yh[s1 * CC + qo]);
    red_h8(&g_aggh[d0 * CC + qo], y0);
    if (q0lane) atomicAdd(&g_degi[d0], 1);
    if (h1) {
        red_h8(&g_aggh[d1 * CC + qo], y1);
        if (q0lane) atomicAdd(&g_degi[d1], 1);
    }
}

// ---------------- head: 2 lanes per node; self-cleans g_degi ----------------
__global__ void k_head(const float* __restrict__ bias,
                       const float* __restrict__ l1w,  // [16,8]
                       const float* __restrict__ l1b,
                       const float* __restrict__ ow,   // [8,1]
                       const float* __restrict__ ob,
                       const float* __restrict__ labels,
                       const float* __restrict__ wts,
                       float* __restrict__ pout, float* losss,
                       int n, float inv_n) {
    __shared__ float sb[CC], sl1w[CC * L1], sl1b[L1], sow[L1], sob;
    if (threadIdx.x < CC) sb[threadIdx.x] = bias[threadIdx.x];
    if (threadIdx.x < CC * L1) sl1w[threadIdx.x] = l1w[threadIdx.x];
    if (threadIdx.x < L1) { sl1b[threadIdx.x] = l1b[threadIdx.x]; sow[threadIdx.x] = ow[threadIdx.x]; }
    if (threadIdx.x == 0) sob = ob[0];
    __syncthreads();

    int t = blockIdx.x * blockDim.x + threadIdx.x;
    int i = t >> 1;            // node
    int a = t & 1;             // which 8-channel half
    float term = 0.0f;
    if (i < n) {
        int degc = __ldg(&g_degi[i]);
        uint4 r = *(const uint4*)&g_aggh[i * CC + a * 8];
        if (a == 0) g_degi[i] = 0;                  // reset for next graph replay
        float invdeg = __fdividef(1.0f, (float)(degc + 1));   // + self loop
        float h[8];
        {
            const unsigned rr[4] = {r.x, r.y, r.z, r.w};
#pragma unroll
            for (int k = 0; k < 4; k++) {
                float2 f = __half22float2(*(const __half2*)&rr[k]);
                h[2 * k]     = f.x;
                h[2 * k + 1] = f.y;
            }
        }
        int cbase = a * 8;
#pragma unroll
        for (int k = 0; k < 8; k++)
            h[k] = fmaxf(fmaf(h[k], invdeg, sb[cbase + k]), 0.0f);

        float s[L1];
#pragma unroll
        for (int j = 0; j < L1; j++) {
            float acc = 0.0f;
#pragma unroll
            for (int k = 0; k < 8; k++)
                acc = fmaf(h[k], sl1w[(cbase + k) * L1 + j], acc);
            s[j] = acc;
        }
        float z = 0.0f;
#pragma unroll
        for (int j = 0; j < L1; j++) {
            float sj = s[j] + __shfl_xor_sync(0xFFFFFFFFu, s[j], 1);
            float h2 = fmaxf(sj + sl1b[j], 0.0f);
            z = fmaf(h2, sow[j], z);
        }
        if (a == 0) {
            z += sob;
            float p = 1.0f / (1.0f + __expf(-z));
            pout[i] = p;
            const float eps = 1e-7f;
            float pc = fminf(fmaxf(p, eps), 1.0f - eps);
            float sel = (labels[i] > 0.5f) ? pc : (1.0f - pc);  // labels exactly 0/1
            term = wts[i] * (-__logf(sel)) * inv_n;
        }
    }
    // block reduce -> one atomic per block
#pragma unroll
    for (int off = 16; off > 0; off >>= 1)
        term += __shfl_down_sync(0xFFFFFFFFu, term, off);
    __shared__ float wsum[8];
    int wid = threadIdx.x >> 5, lid = threadIdx.x & 31;
    if (lid == 0) wsum[wid] = term;
    __syncthreads();
    if (threadIdx.x == 0 && losss) {
        float sum = 0.0f;
#pragma unroll
        for (int k = 0; k < (int)(blockDim.x >> 5); k++) sum += wsum[k];
        atomicAdd(losss, sum);
    }
}

// ---------------- launch ----------------
extern "C" void kernel_launch(void* const* d_in, const int* in_sizes, int n_in,
                              void* d_out, int out_size) {
    const float* x      = (const float*)d_in[0];
    const void*  ei     = d_in[1];
    const float* labels = (const float*)d_in[2];
    const float* wts    = (const float*)d_in[3];
    const float* W      = (const float*)d_in[4];
    // d_in[5]=u, d_in[6]=c unused (H=1 softmax == 1)
    const float* bias   = (const float*)d_in[7];
    const float* l1w    = (const float*)d_in[8];
    const float* l1b    = (const float*)d_in[9];
    const float* ow     = (const float*)d_in[10];
    const float* ob     = (const float*)d_in[11];

    int n = in_sizes[0] / FF;
    int E = in_sizes[1] / 2;

    float* out = (float*)d_out;
    int loss_slot = (out_size == n + 1) ? 1 : 0;
    float* pout  = loss_slot ? (out + 1) : out;
    float* losss = loss_slot ? out : (float*)0;

    k_proj<<<(n + 63) / 64, 256>>>(x, W, ei, losss, n);

    long long threads = ((long long)E + 1) / 2 * 2;   // 2 threads per edge pair
    k_edge<<<(int)((threads + 511) / 512), 512>>>(ei, E);

    k_head<<<(n * 2 + 255) / 256, 256>>>(bias, l1w, l1b, ow, ob, labels, wts,
                                         pout, losss, n, 1.0f / (float)n);
}